// round 4
// baseline (speedup 1.0000x reference)
#include <cuda_runtime.h>
#include <cstdint>

#define Bn 4
#define Cn 7
#define Hn 512
#define Wn 1024
#define HW (Hn*Wn)
#define NID 7
#define NBINS 4096
#define BIN_SCALE 2048.0f             /* NBINS / 2.0 : errors live in [0,2] */
#define XSTEP (2.0f/2047.0f)
#define YSTEP (1.0f/1023.0f)
#define NBLK1 256                     /* phase1 grid = 64 x Bn */

// ---- scratch (static device memory; zero-initialized at module load).
// Invariant: every run leaves all of this zeroed again (scan writes back
// zeros after staging; the last scan block resets the scalar accumulators),
// so graph replays are deterministic.
__device__ unsigned g_hist[Bn*NID*NBINS*2];   // [b][id][bin][{neg,pos}] 0.92MB
__device__ double   g_stats[Bn*NID*7];        // cnt, Sx, Sy, Ss0, Ss1, Sq0, Sq1
__device__ float    g_params[Bn*NID*4];       // c0, c1, sexp0, sexp1
__device__ double   g_seedfg[Bn*NID];
__device__ double   g_cls[Bn*4];              // focal_sum, valid_cnt, seed_bg, pad
__device__ float    g_instl[Bn*NID];
__device__ unsigned g_c1, g_c2;               // completion counters

// ------------------------------------------------------------------
// Phase 1: per-(b,id) stats fully in registers; last block runs "prep"
// (centers + exp(10*mean sigma)) and resets the counter.
__global__ __launch_bounds__(256) void phase1_kernel(
        const float* __restrict__ pred, const int* __restrict__ inst) {
    __shared__ float sh[NID*7];
    __shared__ unsigned s_done;
    int tid = threadIdx.x;
    int lane = tid & 31;
    if (tid < NID*7) sh[tid] = 0.f;
    __syncthreads();

    float acc[NID][7];
    #pragma unroll
    for (int id = 0; id < NID; id++)
        #pragma unroll
        for (int k = 0; k < 7; k++) acc[id][k] = 0.f;

    int b = blockIdx.y;
    const float* s0p = pred + ((size_t)b*Cn + 2)*HW;
    const float* s1p = pred + ((size_t)b*Cn + 3)*HW;
    const int*   ip  = inst + (size_t)b*HW;

    for (int i = blockIdx.x*blockDim.x + tid; i < HW; i += blockDim.x*gridDim.x) {
        int v = ip[i];
        if (v >= 1) {
            float x = (float)(i & (Wn-1)) * XSTEP;
            float y = (float)(i >> 10)    * YSTEP;
            float a = s0p[i], c = s1p[i];
            float a2 = a*a, c2 = c*c;
            #pragma unroll
            for (int id = 0; id < NID; id++) {
                float m = (v == id+1) ? 1.f : 0.f;
                acc[id][0] += m;
                acc[id][1] = fmaf(m, x,  acc[id][1]);
                acc[id][2] = fmaf(m, y,  acc[id][2]);
                acc[id][3] = fmaf(m, a,  acc[id][3]);
                acc[id][4] = fmaf(m, c,  acc[id][4]);
                acc[id][5] = fmaf(m, a2, acc[id][5]);
                acc[id][6] = fmaf(m, c2, acc[id][6]);
            }
        }
    }

    float* af = (float*)acc;
    #pragma unroll
    for (int k = 0; k < NID*7; k++) {
        float v = af[k];
        #pragma unroll
        for (int o = 16; o > 0; o >>= 1) v += __shfl_down_sync(0xffffffffu, v, o);
        if (lane == 0) atomicAdd(&sh[k], v);
    }
    __syncthreads();
    if (tid < NID*7) atomicAdd(&g_stats[b*NID*7 + tid], (double)sh[tid]);

    // last block -> prep
    __threadfence();
    if (tid == 0) s_done = atomicAdd(&g_c1, 1u);
    __syncthreads();
    if (s_done == NBLK1 - 1) {
        if (tid < Bn*NID) {
            const double* s = &g_stats[tid*7];
            double cnt = s[0];
            double cn = cnt > 1.0 ? cnt : 1.0;
            g_params[tid*4+0] = (float)(s[1]/cn);
            g_params[tid*4+1] = (float)(s[2]/cn);
            g_params[tid*4+2] = (float)exp(10.0 * s[3]/cn);
            g_params[tid*4+3] = (float)exp(10.0 * s[4]/cn);
        }
        if (tid == 0) g_c1 = 0u;
    }
}

// ------------------------------------------------------------------
__device__ __forceinline__ float fast_tanh(float x) {
    float t = __expf(-2.0f * fabsf(x));
    float r = __fdividef(1.0f - t, 1.0f + t);
    return copysignf(r, x);
}

// Phase 2: per pixel -> 7 dist evals -> error histogram via global REDG;
// seed_fg / focal / seed_bg accumulated in registers.
__global__ __launch_bounds__(256) void phase2_kernel(
        const float* __restrict__ pred, const int* __restrict__ inst,
        const int* __restrict__ lab) {
    __shared__ float sh[NID + 3];
    int tid = threadIdx.x;
    int lane = tid & 31;
    int b = blockIdx.y;
    if (tid < NID + 3) sh[tid] = 0.f;
    __syncthreads();

    float4 prm[NID];
    #pragma unroll
    for (int id = 0; id < NID; id++)
        prm[id] = __ldg(((const float4*)g_params) + b*NID + id);

    const float* p0p = pred + ((size_t)b*Cn + 0)*HW;
    const float* p1p = pred + ((size_t)b*Cn + 1)*HW;
    const float* p4p = pred + ((size_t)b*Cn + 4)*HW;
    const float* p5p = pred + ((size_t)b*Cn + 5)*HW;
    const float* p6p = pred + ((size_t)b*Cn + 6)*HW;
    const int*   ip  = inst + (size_t)b*HW;
    const int*   lp  = lab  + (size_t)b*HW;
    unsigned* hb = g_hist + (size_t)b*NID*NBINS*2;

    float sfg[NID];
    #pragma unroll
    for (int id = 0; id < NID; id++) sfg[id] = 0.f;
    float clsS = 0.f, vcnt = 0.f, sbg = 0.f;

    for (int i = blockIdx.x*blockDim.x + tid; i < HW; i += blockDim.x*gridDim.x) {
        int v = ip[i];
        int l = lp[i];
        float x = (float)(i & (Wn-1)) * XSTEP;
        float y = (float)(i >> 10)    * YSTEP;
        float e0 = fast_tanh(p0p[i]) + x;
        float e1 = fast_tanh(p1p[i]) + y;
        float seed = __fdividef(1.f, 1.f + __expf(-p4p[i]));

        #pragma unroll
        for (int id = 0; id < NID; id++) {
            float dx = e0 - prm[id].x;
            float dy = e1 - prm[id].y;
            float q  = fmaf(dx*dx, prm[id].z, dy*dy*prm[id].w);
            float d  = __expf(-q);
            bool pos = (v == id + 1);
            float e  = pos ? fmaf(-2.f, d, 2.f) : 2.f*d;
            int bin = (int)(e * BIN_SCALE);
            bin = bin < NBINS-1 ? bin : NBINS-1;
            bin = bin > 0 ? bin : 0;
            atomicAdd(hb + (((size_t)id*NBINS + bin) << 1) + (pos ? 1 : 0), 1u);
            if (pos) { float df = seed - d; sfg[id] = fmaf(df, df, sfg[id]); }
        }
        if (l < 2) {
            float xt = l ? p6p[i] : p5p[i];
            float xo = l ? p5p[i] : p6p[i];
            float u = __expf(xo - xt);
            float logpt = -log1pf(u);
            float pt = __fdividef(1.f, 1.f + u);
            float om = 1.f - pt;
            clsS += -om*om*logpt;
            vcnt += 1.f;
        }
        if (l == 0) sbg += seed*seed;
    }

    float vals[NID + 3];
    #pragma unroll
    for (int id = 0; id < NID; id++) vals[id] = sfg[id];
    vals[NID+0] = clsS; vals[NID+1] = vcnt; vals[NID+2] = sbg;
    #pragma unroll
    for (int k = 0; k < NID + 3; k++) {
        float v = vals[k];
        #pragma unroll
        for (int o = 16; o > 0; o >>= 1) v += __shfl_down_sync(0xffffffffu, v, o);
        if (lane == 0) atomicAdd(&sh[k], v);
    }
    __syncthreads();
    if (tid < NID) atomicAdd(&g_seedfg[b*NID + tid], (double)sh[tid]);
    else if (tid < NID + 3) atomicAdd(&g_cls[b*4 + (tid - NID)], (double)sh[tid]);
}

// ------------------------------------------------------------------
// Scan + final: one block per (b,id). Stages the histogram into smem with
// coalesced loads (writing zeros back for the next run), walks it in
// descending-error order, then the last block computes the output scalar
// and resets all accumulators.
__global__ __launch_bounds__(512) void scan_kernel(float* out) {
    __shared__ uint2 hs[NBINS];               // 32KB
    __shared__ unsigned sp[512], sn[512];
    __shared__ float red[16];
    __shared__ unsigned s_done;
    __shared__ double shP[Bn*NID], shV[Bn*NID], shI[Bn*NID], shS[Bn*NID];
    int t = threadIdx.x;
    int bi = blockIdx.x;                       // 0..27
    uint2* h = (uint2*)g_hist + (size_t)bi*NBINS;

    for (int i = t; i < NBINS; i += 512) {     // coalesced stage + clear
        hs[i] = h[i];
        h[i] = make_uint2(0u, 0u);
    }
    __syncthreads();

    const int BPT = NBINS/512;                 // 8 bins per thread
    unsigned lp = 0, ln = 0;
    int r0 = t * BPT;
    #pragma unroll
    for (int k = 0; k < BPT; k++) {
        uint2 c = hs[NBINS-1 - (r0 + k)];
        ln += c.x; lp += c.y;                  // .x = neg, .y = pos
    }
    sp[t] = lp; sn[t] = ln;
    __syncthreads();
    for (int o = 1; o < 512; o <<= 1) {        // Hillis-Steele inclusive scan
        unsigned a = 0, bsum = 0;
        if (t >= o) { a = sp[t-o]; bsum = sn[t-o]; }
        __syncthreads();
        sp[t] += a; sn[t] += bsum;
        __syncthreads();
    }
    unsigned Ptot = sp[511];

    float acc = 0.f;
    if (Ptot > 0) {
        float P = (float)Ptot;
        float p = (float)(sp[t] - lp);         // exclusive prefix (descending)
        float n = (float)(sn[t] - ln);
        const float escale = 2.0f / (float)NBINS;
        #pragma unroll
        for (int k = 0; k < BPT; k++) {
            int bin = NBINS-1 - (r0 + k);
            uint2 c = hs[bin];
            if (c.x | c.y) {
                float cp = (float)c.y, cn = (float)c.x;
                float num = cp*(P + n) + cn*(P - p);
                float den = (P + n) * (P + n + cn);
                float ec  = ((float)bin + 0.5f) * escale;
                acc += ec * __fdividef(num, den);
                p += cp; n += cn;
            }
        }
    }
    #pragma unroll
    for (int o = 16; o > 0; o >>= 1) acc += __shfl_down_sync(0xffffffffu, acc, o);
    if ((t & 31) == 0) red[t >> 5] = acc;
    __syncthreads();
    if (t < 32) {
        float v = (t < 16) ? red[t] : 0.f;
        #pragma unroll
        for (int o = 8; o > 0; o >>= 1) v += __shfl_down_sync(0xffffffffu, v, o);
        if (t == 0) g_instl[bi] = v;
    }

    // ---- last block: final reduction + state reset ----
    __threadfence();
    if (t == 0) s_done = atomicAdd(&g_c2, 1u);
    __syncthreads();
    if (s_done != Bn*NID - 1) return;

    if (t < Bn*NID) {
        const double* s = &g_stats[t*7];
        double cnt = s[0];
        double pres = 0.0, var = 0.0, inl = 0.0, sf = 0.0;
        if (cnt > 0.0) {
            double m0 = s[3]/cnt, m1 = s[4]/cnt;
            pres = 1.0;
            var = ((s[5] - cnt*m0*m0) + (s[6] - cnt*m1*m1)) / (2.0*cnt);
            inl = (double)g_instl[t];
            sf  = 200.0 * g_seedfg[t];
        }
        shP[t] = pres; shV[t] = var; shI[t] = inl; shS[t] = sf;
    }
    __syncthreads();
    if (t == 0) {
        double totalL = 0.0, totalC = 0.0;
        for (int b = 0; b < Bn; b++) {
            double obj = 0.0, iS = 0.0, vS = 0.0, sS = 0.0;
            for (int id = 0; id < NID; id++) {
                int k = b*NID + id;
                obj += shP[k]; iS += shI[k]; vS += shV[k]; sS += shS[k];
            }
            if (obj < 1.0) obj = 1.0;
            double seed_loss = (g_cls[b*4+2] + sS) / (double)HW;
            totalL += iS/obj + 10.0*(vS/obj) + seed_loss;
            double vc = g_cls[b*4+1]; if (vc < 1.0) vc = 1.0;
            totalC += g_cls[b*4+0] / vc;
        }
        out[0] = (float)((totalL + totalC) / (double)Bn);
    }
    __syncthreads();
    // reset accumulators for the next graph replay
    for (int i = t; i < Bn*NID*7; i += 512) g_stats[i] = 0.0;
    for (int i = t; i < Bn*NID;   i += 512) g_seedfg[i] = 0.0;
    for (int i = t; i < Bn*4;     i += 512) g_cls[i] = 0.0;
    if (t == 0) g_c2 = 0u;
}

// ------------------------------------------------------------------
extern "C" void kernel_launch(void* const* d_in, const int* in_sizes, int n_in,
                              void* d_out, int out_size) {
    const float* pred = (const float*)d_in[0];
    const int*   inst = (const int*)d_in[1];
    const int*   lab  = (const int*)d_in[2];
    float* out = (float*)d_out;

    phase1_kernel<<<dim3(64, Bn), 256>>>(pred, inst);
    phase2_kernel<<<dim3(256, Bn), 256>>>(pred, inst, lab);
    scan_kernel<<<Bn*NID, 512>>>(out);
}